// round 17
// baseline (speedup 1.0000x reference)
#include <cuda_runtime.h>
#include <cuda_fp16.h>
#include <math.h>

#define Bb 4
#define Nn 128
#define Ll 20
#define Dd 512
#define SCALE 0.044194173824159216f  // 1/sqrt(512)
#define FSK 4                         // split-K factor for front GEMMs
#define FCH (Dd / FSK)                // 128

// ---------------- scratch (no allocations allowed) ----------------
__device__ float g_kp [FSK*Bb*Ll*Dd];    // k partials (no bias)    [4][80][512]
__device__ float g_up [FSK*Bb*Ll*Dd];    // u partials              [4][80][512]
__device__ float g_fbq[Bb*Nn*Dd];        // gated boundary feats    [512,512]
__device__ float g_S  [Bb*Nn*Nn];        // A_b after softmax       [4,128,128]

__device__ __forceinline__ unsigned tanh2_f16(unsigned x) {
    unsigned y; asm("tanh.approx.f16x2 %0, %1;" : "=r"(y) : "r"(x)); return y;
}

#define KSTRIDE ((long)Bb*Ll*Dd)

// ======== split-K NT GEMM: kp[s] = f_w @ Wk^T (chunk s), BM=16 BN=32, 128 thr ====
__global__ void gemm_nt_sk(const float* __restrict__ A, const float* __restrict__ Bm,
                           float* __restrict__ Cp)
{
    const int K = Dd;
    int s  = blockIdx.z;
    int kb = s * FCH;
    int bm = blockIdx.y * 16;
    int bn = blockIdx.x * 32;

    __shared__ float Ast[2][32][18];
    __shared__ float Bst[2][32][36];

    int tid = threadIdx.x;
    int r  = tid >> 3;
    int c4 = (tid & 7) * 4;
    int brow0 = tid >> 3;
    int brow1 = brow0 + 16;

    float4 av, bv0, bv1;
    av  = *(const float4*)(A  + (long)(bm + r) * K + kb + c4);
    bv0 = *(const float4*)(Bm + (long)(bn + brow0) * K + kb + c4);
    bv1 = *(const float4*)(Bm + (long)(bn + brow1) * K + kb + c4);
    Ast[0][c4+0][r]=av.x; Ast[0][c4+1][r]=av.y; Ast[0][c4+2][r]=av.z; Ast[0][c4+3][r]=av.w;
    Bst[0][c4+0][brow0]=bv0.x; Bst[0][c4+1][brow0]=bv0.y;
    Bst[0][c4+2][brow0]=bv0.z; Bst[0][c4+3][brow0]=bv0.w;
    Bst[0][c4+0][brow1]=bv1.x; Bst[0][c4+1][brow1]=bv1.y;
    Bst[0][c4+2][brow1]=bv1.z; Bst[0][c4+3][brow1]=bv1.w;
    __syncthreads();

    float a0=0.f, a1=0.f, a2=0.f, a3=0.f;
    const int nit = FCH / 32;     // 4
    int buf = 0;
    for (int it = 0; it < nit; it++) {
        bool more = (it + 1 < nit);
        if (more) {
            int k0n = kb + (it + 1) * 32;
            av  = *(const float4*)(A  + (long)(bm + r) * K + k0n + c4);
            bv0 = *(const float4*)(Bm + (long)(bn + brow0) * K + k0n + c4);
            bv1 = *(const float4*)(Bm + (long)(bn + brow1) * K + k0n + c4);
        }
#pragma unroll
        for (int k = 0; k < 32; k++) {
            float a = Ast[buf][k][r];
            float4 b = *(const float4*)&Bst[buf][k][c4];
            a0 = fmaf(a, b.x, a0);
            a1 = fmaf(a, b.y, a1);
            a2 = fmaf(a, b.z, a2);
            a3 = fmaf(a, b.w, a3);
        }
        if (more) {
            int nb = buf ^ 1;
            Ast[nb][c4+0][r]=av.x; Ast[nb][c4+1][r]=av.y;
            Ast[nb][c4+2][r]=av.z; Ast[nb][c4+3][r]=av.w;
            Bst[nb][c4+0][brow0]=bv0.x; Bst[nb][c4+1][brow0]=bv0.y;
            Bst[nb][c4+2][brow0]=bv0.z; Bst[nb][c4+3][brow0]=bv0.w;
            Bst[nb][c4+0][brow1]=bv1.x; Bst[nb][c4+1][brow1]=bv1.y;
            Bst[nb][c4+2][brow1]=bv1.z; Bst[nb][c4+3][brow1]=bv1.w;
            __syncthreads();
            buf = nb;
        }
    }

    int gm = bm + r, gn = bn + c4;
    float* o = Cp + ((long)s * Bb * Ll + gm) * Dd + gn;
    o[0] = a0; o[1] = a1; o[2] = a2; o[3] = a3;
}

// sum 4 k-partials + bias at (row, col..col+3)
__device__ __forceinline__ float4 ksum4(const float* __restrict__ kp,
                                        const float* __restrict__ bk,
                                        int row, int col)
{
    const float* p = kp + (long)row * Dd + col;
    float4 a = *(const float4*)(p);
    float4 b = *(const float4*)(p + KSTRIDE);
    float4 c = *(const float4*)(p + 2 * KSTRIDE);
    float4 d = *(const float4*)(p + 3 * KSTRIDE);
    float4 e = *(const float4*)(bk + col);
    return make_float4(a.x+b.x+c.x+d.x+e.x, a.y+b.y+c.y+d.y+e.y,
                       a.z+b.z+c.z+d.z+e.z, a.w+b.w+c.w+d.w+e.w);
}

// ======== split-K NN GEMM: up[s] = k @ Wq (chunk s); k summed from partials ====
__global__ void gemm_nn_sk(const float* __restrict__ kp, const float* __restrict__ bk,
                           const float* __restrict__ Bm, float* __restrict__ Cp)
{
    int s  = blockIdx.z;
    int kb = s * FCH;
    int bm = blockIdx.y * 16;
    int bn = blockIdx.x * 32;

    __shared__ float Ast[2][32][18];
    __shared__ float Bst[2][32][36];

    int tid = threadIdx.x;
    int r  = tid >> 3;
    int c4 = (tid & 7) * 4;
    int bkr0 = tid >> 3;
    int bkr1 = bkr0 + 16;

    float4 av, bv0, bv1;
    av  = ksum4(kp, bk, bm + r, kb + c4);
    bv0 = *(const float4*)(Bm + (long)(kb + bkr0) * Dd + bn + c4);
    bv1 = *(const float4*)(Bm + (long)(kb + bkr1) * Dd + bn + c4);
    Ast[0][c4+0][r]=av.x; Ast[0][c4+1][r]=av.y; Ast[0][c4+2][r]=av.z; Ast[0][c4+3][r]=av.w;
    *(float4*)&Bst[0][bkr0][c4] = bv0;
    *(float4*)&Bst[0][bkr1][c4] = bv1;
    __syncthreads();

    float a0=0.f, a1=0.f, a2=0.f, a3=0.f;
    const int nit = FCH / 32;     // 4
    int buf = 0;
    for (int it = 0; it < nit; it++) {
        bool more = (it + 1 < nit);
        if (more) {
            int k0n = kb + (it + 1) * 32;
            av  = ksum4(kp, bk, bm + r, k0n + c4);
            bv0 = *(const float4*)(Bm + (long)(k0n + bkr0) * Dd + bn + c4);
            bv1 = *(const float4*)(Bm + (long)(k0n + bkr1) * Dd + bn + c4);
        }
#pragma unroll
        for (int k = 0; k < 32; k++) {
            float a = Ast[buf][k][r];
            float4 b = *(const float4*)&Bst[buf][k][c4];
            a0 = fmaf(a, b.x, a0);
            a1 = fmaf(a, b.y, a1);
            a2 = fmaf(a, b.z, a2);
            a3 = fmaf(a, b.w, a3);
        }
        if (more) {
            int nb = buf ^ 1;
            Ast[nb][c4+0][r]=av.x; Ast[nb][c4+1][r]=av.y;
            Ast[nb][c4+2][r]=av.z; Ast[nb][c4+3][r]=av.w;
            *(float4*)&Bst[nb][bkr0][c4] = bv0;
            *(float4*)&Bst[nb][bkr1][c4] = bv1;
            __syncthreads();
            buf = nb;
        }
    }

    int gm = bm + r, gn = bn + c4;
    float* o = Cp + ((long)s * Bb * Ll + gm) * Dd + gn;
    o[0] = a0; o[1] = a1; o[2] = a2; o[3] = a3;
}

// ------- cross attention: 8 rows per block; sums u/k partials while staging ----
#define CROSS_SMEM ((2*Ll*Dd + 8*Dd + 32 + 160 + 160) * (int)sizeof(float))
__global__ void cross_attn8(const float* __restrict__ up,
                            const float* __restrict__ kp,
                            const float* __restrict__ bk,
                            const float* __restrict__ bq,
                            const float* __restrict__ f_w,
                            const float* __restrict__ f_b,
                            const float* __restrict__ f_s,
                            float* __restrict__ fbq)
{
    extern __shared__ float sm[];
    float* uw  = sm;                       // [Ll][Dd] (summed u)
    float* fw  = sm + Ll * Dd;             // [Ll][Dd]
    float* fbs = fw + Ll * Dd;             // [8][Dd]
    float* cv  = fbs + 8 * Dd;             // [Ll] (+pad)
    float* lg  = cv + 32;                  // [160]
    float* wt  = lg + 160;                 // [160]

    int b  = blockIdx.y;
    int n0 = blockIdx.x * 8;
    int t  = threadIdx.x;                  // 512
    int w = t >> 5, lane = t & 31;

    const float4* us0 = (const float4*)(up + (long)b * Ll * Dd);
    const float4* us1 = (const float4*)(up + KSTRIDE + (long)b * Ll * Dd);
    const float4* us2 = (const float4*)(up + 2 * KSTRIDE + (long)b * Ll * Dd);
    const float4* us3 = (const float4*)(up + 3 * KSTRIDE + (long)b * Ll * Dd);
    const float4* fws = (const float4*)(f_w + (long)b * Ll * Dd);
    for (int i = t; i < (Ll * Dd) / 4; i += 512) {
        float4 a = us0[i], bb = us1[i], c = us2[i], d = us3[i];
        ((float4*)uw)[i] = make_float4(a.x+bb.x+c.x+d.x, a.y+bb.y+c.y+d.y,
                                       a.z+bb.z+c.z+d.z, a.w+bb.w+c.w+d.w);
        ((float4*)fw)[i] = fws[i];
    }
    const float4* fbsrc = (const float4*)(f_b + (long)(b * Nn + n0) * Dd);
    for (int i = t; i < (8 * Dd) / 4; i += 512) ((float4*)fbs)[i] = fbsrc[i];

    // cv[l] = bq . (k[b,l] summed + bk)
    for (int l = w; l < Ll; l += 16) {
        const float* kr = kp + (long)(b * Ll + l) * Dd;
        float p = 0.f;
#pragma unroll
        for (int dd = 0; dd < Dd / 32; dd++) {
            int idx = lane + dd * 32;
            float kv = kr[idx] + kr[KSTRIDE + idx] + kr[2*KSTRIDE + idx]
                     + kr[3*KSTRIDE + idx] + bk[idx];
            p = fmaf(bq[idx], kv, p);
        }
#pragma unroll
        for (int off = 16; off > 0; off >>= 1) p += __shfl_xor_sync(0xffffffff, p, off);
        if (lane == 0) cv[l] = p;
    }
    __syncthreads();

    for (int idx = w; idx < 8 * Ll; idx += 16) {
        int n = idx & 7, l = idx >> 3;
        const float* fr = fbs + n * Dd;
        const float* ur = uw + l * Dd;
        float p = 0.f;
#pragma unroll
        for (int dd = 0; dd < Dd / 32; dd++)
            p = fmaf(fr[lane + dd * 32], ur[lane + dd * 32], p);
#pragma unroll
        for (int off = 16; off > 0; off >>= 1) p += __shfl_xor_sync(0xffffffff, p, off);
        if (lane == 0) lg[l * 8 + n] = (p + cv[l]) * SCALE;
    }
    __syncthreads();

    if (t < 8) {
        float mx = -1e30f;
#pragma unroll
        for (int l = 0; l < Ll; l++) mx = fmaxf(mx, lg[l * 8 + t]);
        float sum = 0.f;
#pragma unroll
        for (int l = 0; l < Ll; l++) { float e = __expf(lg[l * 8 + t] - mx); wt[l * 8 + t] = e; sum += e; }
        float inv = __fdividef(1.f, sum);
#pragma unroll
        for (int l = 0; l < Ll; l++) wt[l * 8 + t] *= inv;
    }
    __syncthreads();

    float fsv = f_s[(long)b * Dd + t];
#pragma unroll
    for (int n = 0; n < 8; n++) {
        float acc = 0.f;
#pragma unroll
        for (int l = 0; l < Ll; l++) acc = fmaf(wt[l * 8 + n], fw[l * Dd + t], acc);
        float v = fbs[n * Dd + t] * (acc + fsv);
        fbq[(long)(b * Nn + n0 + n) * Dd + t] = v;
    }
}

// -------- fused: S tile (recomputed) + row softmax + fbb GEMM ----------------
// grid (Dd/64=8, Nn/32=4, Bb) = 128 blocks, 256 threads.
// Each block recomputes its 32x128 S tile from fbq (K=512), softmaxes rows,
// writes A_b to S (x==0 blocks only) and out = A_b@f_b + f_b for its d-tile.
__global__ void sfbb_kernel(const float* __restrict__ fbq, const float* __restrict__ f_b,
                            float* __restrict__ S, float* __restrict__ out)
{
    int b  = blockIdx.z;
    int rt = blockIdx.y * 32;
    int dt = blockIdx.x * 64;
    const float* A = fbq + (long)b * Nn * Dd;

    __shared__ union SmU {
        struct { float Ach[64][34]; float Bch[64][132]; } s1;   // k-chunk staging
        struct { float Sm[Nn][34]; float Bst[32][68]; } s2;     // S tile + fbb staging
    } smu;

    int tid = threadIdx.x;
    int tr = tid >> 4;            // 0..15 -> rows 2tr..2tr+1
    int tc = tid & 15;            // 0..15 -> cols 8tc..8tc+7

    float acc[2][8];
#pragma unroll
    for (int i = 0; i < 2; i++)
#pragma unroll
        for (int j = 0; j < 8; j++) acc[i][j] = 0.f;

    for (int k0 = 0; k0 < Dd; k0 += 64) {
        // stage A chunk: 32 rows x 64 k, [k][r]
        {
            int r = tid >> 3;           // 0..31
            int c8 = (tid & 7) * 8;     // 0..56
            float4 v0 = *(const float4*)(A + (long)(rt + r) * Dd + k0 + c8);
            float4 v1 = *(const float4*)(A + (long)(rt + r) * Dd + k0 + c8 + 4);
            smu.s1.Ach[c8+0][r]=v0.x; smu.s1.Ach[c8+1][r]=v0.y;
            smu.s1.Ach[c8+2][r]=v0.z; smu.s1.Ach[c8+3][r]=v0.w;
            smu.s1.Ach[c8+4][r]=v1.x; smu.s1.Ach[c8+5][r]=v1.y;
            smu.s1.Ach[c8+6][r]=v1.z; smu.s1.Ach[c8+7][r]=v1.w;
        }
        // stage B chunk: all 128 rows x 64 k, [k][m]
        {
            int m = tid >> 1;           // 0..127
            int half = (tid & 1) * 32;  // 0 or 32
#pragma unroll
            for (int q = 0; q < 8; q++) {
                int col = half + q * 4;
                float4 v = *(const float4*)(A + (long)m * Dd + k0 + col);
                smu.s1.Bch[col+0][m]=v.x; smu.s1.Bch[col+1][m]=v.y;
                smu.s1.Bch[col+2][m]=v.z; smu.s1.Bch[col+3][m]=v.w;
            }
        }
        __syncthreads();

#pragma unroll 8
        for (int k = 0; k < 64; k++) {
            float2 a  = *(const float2*)&smu.s1.Ach[k][tr * 2];
            float4 b0 = *(const float4*)&smu.s1.Bch[k][tc * 8];
            float4 b1 = *(const float4*)&smu.s1.Bch[k][tc * 8 + 4];
            acc[0][0] = fmaf(a.x, b0.x, acc[0][0]);
            acc[0][1] = fmaf(a.x, b0.y, acc[0][1]);
            acc[0][2] = fmaf(a.x, b0.z, acc[0][2]);
            acc[0][3] = fmaf(a.x, b0.w, acc[0][3]);
            acc[0][4] = fmaf(a.x, b1.x, acc[0][4]);
            acc[0][5] = fmaf(a.x, b1.y, acc[0][5]);
            acc[0][6] = fmaf(a.x, b1.z, acc[0][6]);
            acc[0][7] = fmaf(a.x, b1.w, acc[0][7]);
            acc[1][0] = fmaf(a.y, b0.x, acc[1][0]);
            acc[1][1] = fmaf(a.y, b0.y, acc[1][1]);
            acc[1][2] = fmaf(a.y, b0.z, acc[1][2]);
            acc[1][3] = fmaf(a.y, b0.w, acc[1][3]);
            acc[1][4] = fmaf(a.y, b1.x, acc[1][4]);
            acc[1][5] = fmaf(a.y, b1.y, acc[1][5]);
            acc[1][6] = fmaf(a.y, b1.z, acc[1][6]);
            acc[1][7] = fmaf(a.y, b1.w, acc[1][7]);
        }
        __syncthreads();
    }

    // write scaled logits into Sm [m][r]
#pragma unroll
    for (int i = 0; i < 2; i++)
#pragma unroll
        for (int j = 0; j < 8; j++)
            smu.s2.Sm[tc * 8 + j][tr * 2 + i] = acc[i][j] * SCALE;
    __syncthreads();

    // row softmax (8 warps x 4 rows); write A_b to S from x==0 blocks
    {
        int w = tid >> 5, lane = tid & 31;
#pragma unroll
        for (int rr = w * 4; rr < w * 4 + 4; rr++) {
            float v[4];
#pragma unroll
            for (int j = 0; j < 4; j++) v[j] = smu.s2.Sm[lane + 32 * j][rr];
            float mx = fmaxf(fmaxf(v[0], v[1]), fmaxf(v[2], v[3]));
#pragma unroll
            for (int off = 16; off > 0; off >>= 1) mx = fmaxf(mx, __shfl_xor_sync(0xffffffff, mx, off));
            float sum = 0.f;
#pragma unroll
            for (int j = 0; j < 4; j++) { v[j] = __expf(v[j] - mx); sum += v[j]; }
#pragma unroll
            for (int off = 16; off > 0; off >>= 1) sum += __shfl_xor_sync(0xffffffff, sum, off);
            float inv = __fdividef(1.f, sum);
#pragma unroll
            for (int j = 0; j < 4; j++) {
                float a = v[j] * inv;
                smu.s2.Sm[lane + 32 * j][rr] = a;
                if (blockIdx.x == 0) S[((long)(b * Nn) + rt + rr) * Nn + lane + 32 * j] = a;
            }
        }
    }
    __syncthreads();

    // fbb: out = A_b @ f_b + f_b for this (rt, dt) tile
    const float* Bf = f_b + (long)b * Nn * Dd;
    int bkr0 = tid >> 4, bkr1 = bkr0 + 16;
    int bcol = (tid & 15) * 4;

    float facc[2][4];
#pragma unroll
    for (int i = 0; i < 2; i++)
#pragma unroll
        for (int j = 0; j < 4; j++) facc[i][j] = 0.f;

    for (int m0 = 0; m0 < Nn; m0 += 32) {
        *(float4*)&smu.s2.Bst[bkr0][bcol] = *(const float4*)(Bf + (long)(m0 + bkr0) * Dd + dt + bcol);
        *(float4*)&smu.s2.Bst[bkr1][bcol] = *(const float4*)(Bf + (long)(m0 + bkr1) * Dd + dt + bcol);
        __syncthreads();
#pragma unroll
        for (int k = 0; k < 32; k++) {
            float2 a = *(const float2*)&smu.s2.Sm[m0 + k][tr * 2];
            float4 bb = *(const float4*)&smu.s2.Bst[k][tc * 4];
            facc[0][0] = fmaf(a.x, bb.x, facc[0][0]);
            facc[0][1] = fmaf(a.x, bb.y, facc[0][1]);
            facc[0][2] = fmaf(a.x, bb.z, facc[0][2]);
            facc[0][3] = fmaf(a.x, bb.w, facc[0][3]);
            facc[1][0] = fmaf(a.y, bb.x, facc[1][0]);
            facc[1][1] = fmaf(a.y, bb.y, facc[1][1]);
            facc[1][2] = fmaf(a.y, bb.z, facc[1][2]);
            facc[1][3] = fmaf(a.y, bb.w, facc[1][3]);
        }
        __syncthreads();
    }

#pragma unroll
    for (int i = 0; i < 2; i++) {
        int gn = rt + tr * 2 + i;
#pragma unroll
        for (int j = 0; j < 4; j++) {
            int gd = dt + tc * 4 + j;
            out[((long)b * Nn + gn) * Dd + gd] = facc[i][j] + Bf[(long)gn * Dd + gd];
        }
    }
}

// -------- gated moment reduction: out += sum_i A[i,j]*fm*sigmoid(fm*s) ----
// f16x2 packed tanh: 2 sigmoids per MUFU issue. fp32 accumulation.
__global__ void moment_kernel(const float* __restrict__ S,
                              const float* __restrict__ f_m,
                              const float* __restrict__ f_s,
                              float* __restrict__ out)
{
    int j = blockIdx.x, b = blockIdx.y;
    int t = threadIdx.x;                  // 0..511
    int dt = t & 127;                     // d-group: d = 4*dt
    int ig = t >> 7;                      // 0..3

    __shared__ float Acol[Nn];
    __shared__ float4 red[4][128];
    if (t < Nn) Acol[t] = S[(long)(b * Nn + t) * Nn + j];
    __syncthreads();

    float4 s = *(const float4*)(f_s + (long)b * Dd + 4 * dt);
    float hx = 0.5f * s.x, hy = 0.5f * s.y, hz = 0.5f * s.z, hw = 0.5f * s.w;
    const float4* fm = (const float4*)(f_m + ((long)(b * Nn) * Nn + j) * Dd) + dt;
    const long istep = (long)Nn * Dd / 4;

    const __half2 h05 = __float2half2_rn(0.5f);
    float ax = 0.f, ay = 0.f, az = 0.f, aw = 0.f;
#pragma unroll 8
    for (int ii = 0; ii < Nn / 4; ii++) {
        int i = ig * (Nn / 4) + ii;
        float4 x = __ldcs(&fm[(long)i * istep]);
        float a = Acol[i];
        __half2 p01 = __floats2half2_rn(x.x * hx, x.y * hy);
        __half2 p23 = __floats2half2_rn(x.z * hz, x.w * hw);
        unsigned u01 = tanh2_f16(*(unsigned*)&p01);
        unsigned u23 = tanh2_f16(*(unsigned*)&p23);
        __half2 s01 = __hfma2(*(__half2*)&u01, h05, h05);
        __half2 s23 = __hfma2(*(__half2*)&u23, h05, h05);
        float2 f01 = __half22float2(s01);
        float2 f23 = __half22float2(s23);
        ax = fmaf(a * x.x, f01.x, ax);
        ay = fmaf(a * x.y, f01.y, ay);
        az = fmaf(a * x.z, f23.x, az);
        aw = fmaf(a * x.w, f23.y, aw);
    }
    red[ig][dt] = make_float4(ax, ay, az, aw);
    __syncthreads();

    if (t < 128) {
        float4 r0 = red[0][t], r1 = red[1][t], r2 = red[2][t], r3 = red[3][t];
        float4* op = (float4*)(out + (long)(b * Nn + j) * Dd) + t;
        float4 r = *op;
        r.x += r0.x + r1.x + r2.x + r3.x;
        r.y += r0.y + r1.y + r2.y + r3.y;
        r.z += r0.z + r1.z + r2.z + r3.z;
        r.w += r0.w + r1.w + r2.w + r3.w;
        *op = r;
    }
}

// ---------------- launch ----------------
extern "C" void kernel_launch(void* const* d_in, const int* in_sizes, int n_in,
                              void* d_out, int out_size)
{
    const float* f_b = (const float*)d_in[0];
    const float* f_w = (const float*)d_in[1];
    const float* f_s = (const float*)d_in[2];
    const float* f_m = (const float*)d_in[3];
    const float* Wq  = (const float*)d_in[4];
    const float* bq  = (const float*)d_in[5];
    const float* Wk  = (const float*)d_in[6];
    const float* bk  = (const float*)d_in[7];
    float* out = (float*)d_out;

    float* kp  = nullptr; cudaGetSymbolAddress((void**)&kp,  g_kp);
    float* up  = nullptr; cudaGetSymbolAddress((void**)&up,  g_up);
    float* fbq = nullptr; cudaGetSymbolAddress((void**)&fbq, g_fbq);
    float* S   = nullptr; cudaGetSymbolAddress((void**)&S,   g_S);

    cudaFuncSetAttribute(cross_attn8, cudaFuncAttributeMaxDynamicSharedMemorySize, CROSS_SMEM);

    // 1) kp[s] = f_w @ Wk^T (chunk s)   [4][80,512]
    {
        dim3 grid(Dd / 32, (Bb * Ll) / 16, FSK);
        gemm_nt_sk<<<grid, 128>>>(f_w, Wk, kp);
    }
    // 2) up[s] = (sum kp + bk) @ Wq (chunk s)
    {
        dim3 grid(Dd / 32, (Bb * Ll) / 16, FSK);
        gemm_nn_sk<<<grid, 128>>>(kp, bk, Wq, up);
    }
    // 3) cross attention + gate -> f_bq (sums partials while staging)
    {
        dim3 grid(Nn / 8, Bb);
        cross_attn8<<<grid, 512, CROSS_SMEM>>>(up, kp, bk, bq, f_w, f_b, f_s, fbq);
    }
    // 4) fused S + softmax + fbb: writes S and out = A_b@f_b + f_b
    {
        dim3 grid(Dd / 64, Nn / 32, Bb);
        sfbb_kernel<<<grid, 256>>>(fbq, f_b, S, out);
    }
    // 5) moment: out += gated moment reduction (f16x2 tanh)
    {
        dim3 grid(Nn, Bb);
        moment_kernel<<<grid, 512>>>(S, f_m, f_s, out);
    }
    (void)in_sizes; (void)n_in; (void)out_size;
}